// round 16
// baseline (speedup 1.0000x reference)
#include <cuda_runtime.h>
#include <cuda_fp16.h>
#include <mma.h>
#include <math.h>
#include <cstdint>

using namespace nvcuda;

#define DIM 2048
#define H 16
#define KVH 4
#define HD 128
#define RD 64
#define BATCH 4
#define T 2048
#define MTOT (BATCH * T)   // 8192
#define SCALE 0.08838834764831845f
#define LOG2_10000 13.287712379549449f

// ---------------- scratch -----------------------------------------------------
__device__ float  g_qlin[MTOT * DIM];
__device__ float  g_klin[MTOT * KVH * HD];
__device__ float  g_vlin[MTOT * KVH * HD];
__device__ __half g_q[BATCH * H * T * HD];
__device__ __half g_k[BATCH * KVH * T * HD];
__device__ __half g_v[BATCH * KVH * T * HD];
__device__ __half g_y[MTOT * DIM];
__device__ __half g_xh[MTOT * DIM];
__device__ __half g_wqh[DIM * DIM];
__device__ __half g_wkh[KVH * HD * DIM];
__device__ __half g_wvh[KVH * HD * DIM];
__device__ __half g_wph[DIM * DIM];

// ---------------- helpers ------------------------------------------------------
__device__ __forceinline__ void cp_async16(void* smem, const void* gmem) {
    unsigned s = (unsigned)__cvta_generic_to_shared(smem);
    asm volatile("cp.async.cg.shared.global [%0], [%1], 16;\n" :: "r"(s), "l"(gmem) : "memory");
}
#define CP_COMMIT asm volatile("cp.async.commit_group;\n" ::: "memory")
#define CP_WAIT0  asm volatile("cp.async.wait_group 0;\n" ::: "memory")
#define CP_WAIT1  asm volatile("cp.async.wait_group 1;\n" ::: "memory")

__device__ __forceinline__ void ldm_x4(uint32_t a, uint32_t& r0, uint32_t& r1,
                                       uint32_t& r2, uint32_t& r3) {
    asm volatile("ldmatrix.sync.aligned.m8n8.x4.shared.b16 {%0,%1,%2,%3}, [%4];"
                 : "=r"(r0), "=r"(r1), "=r"(r2), "=r"(r3) : "r"(a));
}
__device__ __forceinline__ void ldm_x4_t(uint32_t a, uint32_t& r0, uint32_t& r1,
                                         uint32_t& r2, uint32_t& r3) {
    asm volatile("ldmatrix.sync.aligned.m8n8.x4.trans.shared.b16 {%0,%1,%2,%3}, [%4];"
                 : "=r"(r0), "=r"(r1), "=r"(r2), "=r"(r3) : "r"(a));
}
__device__ __forceinline__ void mma16816(float* c, const uint32_t* a, const uint32_t* b) {
    asm volatile("mma.sync.aligned.m16n8k16.row.col.f32.f16.f16.f32 "
                 "{%0,%1,%2,%3}, {%4,%5,%6,%7}, {%8,%9}, {%0,%1,%2,%3};"
                 : "+f"(c[0]), "+f"(c[1]), "+f"(c[2]), "+f"(c[3])
                 : "r"(a[0]), "r"(a[1]), "r"(a[2]), "r"(a[3]), "r"(b[0]), "r"(b[1]));
}
__device__ __forceinline__ uint32_t h2pack(float x, float y) {
    __half2 h = __floats2half2_rn(x, y);
    return *(uint32_t*)&h;
}

// ---------------- fused fp16 conversion of all GEMM operands -------------------
#define N4X 4194304
#define N4Q 1048576
#define N4K 262144
#define N4V 262144
#define N4P 1048576
__global__ void convert_all(
    const float* __restrict__ x, const float* __restrict__ wq,
    const float* __restrict__ wk, const float* __restrict__ wv,
    const float* __restrict__ wp,
    __half* __restrict__ xh, __half* __restrict__ wqh,
    __half* __restrict__ wkh, __half* __restrict__ wvh, __half* __restrict__ wph)
{
    int i = blockIdx.x * blockDim.x + threadIdx.x;
    const float4* src; __half2* dst; int off;
    if (i < N4X)                         { src = (const float4*)x;  dst = (__half2*)xh;  off = 0; }
    else if (i < N4X + N4Q)              { src = (const float4*)wq; dst = (__half2*)wqh; off = N4X; }
    else if (i < N4X + N4Q + N4K)        { src = (const float4*)wk; dst = (__half2*)wkh; off = N4X + N4Q; }
    else if (i < N4X + N4Q + N4K + N4V)  { src = (const float4*)wv; dst = (__half2*)wvh; off = N4X + N4Q + N4K; }
    else                                 { src = (const float4*)wp; dst = (__half2*)wph; off = N4X + N4Q + N4K + N4V; }
    int j = i - off;
    float4 v = src[j];
    dst[j * 2]     = __floats2half2_rn(v.x, v.y);
    dst[j * 2 + 1] = __floats2half2_rn(v.z, v.w);
}

// ---------------- FP16 GEMM, segmented N (round-10 config) ---------------------
// BM=BN=128, BK=32, 8 warps (64x32 each, 2x4), 3-stage cp.async, stride 40 h.
#define GSTR 40
#define GSTG (128 * GSTR)
#define GEMM_SMEM (3 * 2 * GSTG * 2)      // 61440 bytes

__global__ void __launch_bounds__(256, 2) gemm_seg(
    const __half* __restrict__ A, int K,
    const __half* __restrict__ B0, float* __restrict__ C0, int t0, int ldc0,
    const __half* __restrict__ B1, float* __restrict__ C1, int t1, int ldc1,
    const __half* __restrict__ B2, float* __restrict__ C2, int t2, int ldc2)
{
    extern __shared__ __half hsm[];
    const int tid = threadIdx.x;
    const int warp = tid >> 5;
    const int wr = warp >> 2, wc = warp & 3;
    const int bm = blockIdx.y;
    int bn = blockIdx.x;

    const __half* B; float* C; int ldc;
    if (bn < t0)            { B = B0; C = C0; ldc = ldc0; }
    else if (bn < t0 + t1)  { B = B1; C = C1; ldc = ldc1; bn -= t0; }
    else                    { B = B2; C = C2; ldc = ldc2; bn -= t0 + t1; }

    const __half* Ab = A + (size_t)bm * 128 * K;
    const __half* Bb = B + (size_t)bn * 128 * K;

    wmma::fragment<wmma::accumulator, 16, 16, 16, float> acc[4][2];
#pragma unroll
    for (int i = 0; i < 4; i++)
#pragma unroll
        for (int j = 0; j < 2; j++) wmma::fill_fragment(acc[i][j], 0.0f);

    const int ntiles = K >> 5;
#pragma unroll
    for (int s = 0; s < 2; s++) {
        __half* As = hsm + s * 2 * GSTG;
        __half* Bs = As + GSTG;
#pragma unroll
        for (int i = 0; i < 2; i++) {
            int idx = tid + i * 256;
            int r = idx >> 2, c8 = (idx & 3) * 8;
            cp_async16(As + r * GSTR + c8, Ab + (size_t)r * K + s * 32 + c8);
            cp_async16(Bs + r * GSTR + c8, Bb + (size_t)r * K + s * 32 + c8);
        }
        CP_COMMIT;
    }

    for (int kt = 0; kt < ntiles; kt++) {
        CP_WAIT1;
        __syncthreads();
        __half* As = hsm + (kt % 3) * 2 * GSTG;
        __half* Bs = As + GSTG;
#pragma unroll
        for (int kk = 0; kk < 32; kk += 16) {
            wmma::fragment<wmma::matrix_a, 16, 16, 16, __half, wmma::row_major> a[4];
            wmma::fragment<wmma::matrix_b, 16, 16, 16, __half, wmma::col_major> bf[2];
#pragma unroll
            for (int i = 0; i < 4; i++)
                wmma::load_matrix_sync(a[i], As + (wr * 64 + i * 16) * GSTR + kk, GSTR);
#pragma unroll
            for (int j = 0; j < 2; j++)
                wmma::load_matrix_sync(bf[j], Bs + (wc * 32 + j * 16) * GSTR + kk, GSTR);
#pragma unroll
            for (int i = 0; i < 4; i++)
#pragma unroll
                for (int j = 0; j < 2; j++)
                    wmma::mma_sync(acc[i][j], a[i], bf[j], acc[i][j]);
        }
        __syncthreads();
        if (kt + 2 < ntiles) {
            int s = (kt + 2) % 3;
            int k0 = (kt + 2) * 32;
            __half* An = hsm + s * 2 * GSTG;
            __half* Bn = An + GSTG;
#pragma unroll
            for (int i = 0; i < 2; i++) {
                int idx = tid + i * 256;
                int r = idx >> 2, c8 = (idx & 3) * 8;
                cp_async16(An + r * GSTR + c8, Ab + (size_t)r * K + k0 + c8);
                cp_async16(Bn + r * GSTR + c8, Bb + (size_t)r * K + k0 + c8);
            }
        }
        CP_COMMIT;
    }

#pragma unroll
    for (int i = 0; i < 4; i++)
#pragma unroll
        for (int j = 0; j < 2; j++)
            wmma::store_matrix_sync(
                C + (size_t)(bm * 128 + wr * 64 + i * 16) * ldc + bn * 128 + wc * 32 + j * 16,
                acc[i][j], ldc, wmma::mem_row_major);
}

// ---------------- fused RMSNorm+RoPE (q,k) + v reorder, fp16 out ---------------
#define NWQ (BATCH * T * H)
#define NWK (BATCH * T * KVH)
#define NWV (BATCH * T * KVH)
__global__ void rope_fused(
    const float* __restrict__ qlin, const float* __restrict__ klin,
    const float* __restrict__ vlin, const float* __restrict__ gain,
    __half* __restrict__ qout, __half* __restrict__ kout, __half* __restrict__ vout)
{
    int w = (blockIdx.x * blockDim.x + threadIdx.x) >> 5;
    int lane = threadIdx.x & 31;

    if (w < NWQ + NWK) {
        bool isq = (w < NWQ);
        int hh, t, b, nh;
        const float* src;
        if (isq) {
            nh = H;
            hh = w % H; t = (w / H) % T; b = w / (H * T);
            src = qlin + ((size_t)(b * T + t)) * DIM + hh * HD;
        } else {
            int wk = w - NWQ;
            nh = KVH;
            hh = wk % KVH; t = (wk / KVH) % T; b = wk / (KVH * T);
            src = klin + ((size_t)(b * T + t)) * (KVH * HD) + hh * HD;
        }
        float v0 = src[lane], v1 = src[lane + 32], v2 = src[lane + 64], v3 = src[lane + 96];
        float ss = v0 * v0 + v1 * v1 + v2 * v2 + v3 * v3;
#pragma unroll
        for (int o = 16; o; o >>= 1) ss += __shfl_xor_sync(0xffffffffu, ss, o);
        float r = rsqrtf(ss * (1.0f / 128.0f) + 1e-6f);
        v0 *= r; v1 *= r; v2 *= r; v3 *= r;

        float inv = exp2f(-(float)lane * (LOG2_10000 / 32.0f));
        float fr = (float)t * inv;
        float sn, cs;
        sincosf(fr, &sn, &cs);
        float o0 = v0 * cs - v1 * sn;
        float o1 = v1 * cs + v0 * sn;

        float g = isq ? gain[hh] * SCALE : 1.0f;
        __half* dst = (isq ? qout : kout) + (((size_t)(b * nh + hh)) * T + t) * HD;
        dst[lane]      = __float2half_rn(o0 * g);
        dst[lane + 32] = __float2half_rn(o1 * g);
        dst[lane + 64] = __float2half_rn(v2 * g);
        dst[lane + 96] = __float2half_rn(v3 * g);
    } else {
        int u = w - NWQ - NWK;
        int kv = u & 3;
        int bt = u >> 2;
        int t = bt & (T - 1);
        int b = bt >> 11;
        float4 val = ((const float4*)vlin)[u * 32 + lane];
        __half2* dst = (__half2*)(vout + (((size_t)(b * KVH + kv)) * T + t) * HD);
        dst[lane * 2]     = __floats2half2_rn(val.x, val.y);
        dst[lane * 2 + 1] = __floats2half2_rn(val.z, val.w);
    }
}

// ---------------- Flash attention FA2-style (BQ=64, BKV=64, 128 thr) -----------
// smem compacted to 69632 B: K stages at 0/17408, V stages at 34816/52224.
// Q is staged at 52224 (aliasing V stage 1) only during the prologue; qf lives
// in registers afterwards, and the j=0 V-prefetch (first writer of stage 1)
// is issued only after the post-extraction __syncthreads().
// 69632 x 3 = 208896 B -> 3 CTAs/SM (launch_bounds caps regs at 170).
#define QSTR 136
#define FA_SMEM 69632

__global__ void __launch_bounds__(128, 3) flash_kernel(
    const __half* __restrict__ Q, const __half* __restrict__ Kg,
    const __half* __restrict__ Vg, const float* __restrict__ vlin,
    __half* __restrict__ Y)
{
    extern __shared__ char sm[];
    const uint32_t smem_base = (uint32_t)__cvta_generic_to_shared(sm);
    const uint32_t Ks_base = smem_base;            // 2 x 17408
    const uint32_t Vs_base = smem_base + 34816;    // 2 x 17408 (stage 1 aliases Q)

    const int tid = threadIdx.x;
    const int warp = tid >> 5;      // 0..3, owns q rows [warp*16, +16)
    const int lane = tid & 31;
    const int qi = (gridDim.x - 1) - blockIdx.x;   // heavy tiles first
    const int h = blockIdx.y, b = blockIdx.z;
    const int q0 = qi * 64;
    const int kvh = h >> 2;
    const int njt = qi + 1;

    const __half* Qbase = Q + (((size_t)b * H + h) * T + q0) * HD;
    const __half* Kbase = Kg + ((size_t)b * KVH + kvh) * T * HD;
    const __half* Vbase = Vg + ((size_t)b * KVH + kvh) * T * HD;

    // prologue: K0 -> stage0, V0 -> V stage0, Q -> V stage1 region (52224)
#pragma unroll
    for (int i = 0; i < 8; i++) {
        int idx = tid + i * 128;
        int r = idx >> 4, c = idx & 15;
        cp_async16(sm + r * 272 + c * 16, Kbase + r * 128 + c * 8);
        cp_async16(sm + 34816 + r * 272 + c * 16, Vbase + r * 128 + c * 8);
    }
    CP_COMMIT;
#pragma unroll
    for (int i = 0; i < 8; i++) {
        int idx = tid + i * 128;
        int r = idx >> 4, c = idx & 15;
        cp_async16(sm + 52224 + r * 272 + c * 16, Qbase + r * 128 + c * 8);
    }
    CP_COMMIT;
    CP_WAIT0;
    __syncthreads();

    // Q fragments: 8 kk-steps, loop-invariant (extracted from aliased region)
    uint32_t qf[8][4];
    {
        uint32_t qaddr = smem_base + 52224 +
            ((uint32_t)(warp * 16 + (lane & 15)) * QSTR + (uint32_t)(lane >> 4) * 8) * 2;
#pragma unroll
        for (int kk = 0; kk < 8; kk++)
            ldm_x4(qaddr + kk * 32, qf[kk][0], qf[kk][1], qf[kk][2], qf[kk][3]);
    }
    __syncthreads();   // all qf extracted before anyone overwrites stage 1 (V1 prefetch)

    const int g8 = lane >> 3, l8 = lane & 7;
    const uint32_t laneK = (uint32_t)(((g8 >= 2) ? 8 : 0) + l8) * QSTR + ((g8 & 1) ? 8 : 0);
    const uint32_t laneVr = (uint32_t)((g8 & 1) * 8 + l8);
    const uint32_t laneVc = (g8 >= 2) ? 8 : 0;

    const int rowA = q0 + warp * 16 + (lane >> 2);
    const int colb = (lane & 3) * 2;

    float oacc[16][4];
#pragma unroll
    for (int nt = 0; nt < 16; nt++)
#pragma unroll
        for (int e = 0; e < 4; e++) oacc[nt][e] = 0.f;
    float mA = -1e30f, mB = -1e30f, lA = 0.f, lB = 0.f;

    for (int j = 0; j < njt; j++) {
        const int buf = j & 1;
        const uint32_t Ks = Ks_base + buf * 17408;
        const uint32_t Vs = Vs_base + buf * 17408;
        const int kbase = j * 64;

        if (j + 1 < njt) {
            const __half* Kn = Kbase + (size_t)(j + 1) * 8192;
            const __half* Vn = Vbase + (size_t)(j + 1) * 8192;
            char* Kd = sm + (buf ^ 1) * 17408;
            char* Vd = sm + 34816 + (buf ^ 1) * 17408;
#pragma unroll
            for (int i = 0; i < 8; i++) {
                int idx = tid + i * 128;
                int r = idx >> 4, c = idx & 15;
                cp_async16(Kd + r * 272 + c * 16, Kn + r * 128 + c * 8);
                cp_async16(Vd + r * 272 + c * 16, Vn + r * 128 + c * 8);
            }
            CP_COMMIT;
        }

        float sacc[8][4];
#pragma unroll
        for (int nt = 0; nt < 8; nt++)
#pragma unroll
            for (int e = 0; e < 4; e++) sacc[nt][e] = 0.f;
#pragma unroll
        for (int kk = 0; kk < 8; kk++) {
#pragma unroll
            for (int p = 0; p < 4; p++) {
                uint32_t b0, b1, b2, b3;
                ldm_x4(Ks + ((uint32_t)(p * 16) * QSTR + (uint32_t)(kk * 16) + laneK) * 2,
                       b0, b1, b2, b3);
                uint32_t bb0[2] = {b0, b1}, bb1[2] = {b2, b3};
                mma16816(sacc[2 * p],     qf[kk], bb0);
                mma16816(sacc[2 * p + 1], qf[kk], bb1);
            }
        }

        if (kbase + 63 > rowA) {
            int limA = rowA - kbase;
#pragma unroll
            for (int nt = 0; nt < 8; nt++) {
                int c0 = nt * 8 + colb;
                if (c0 > limA)     sacc[nt][0] = -1e30f;
                if (c0 + 1 > limA) sacc[nt][1] = -1e30f;
                if (c0 > limA + 8)     sacc[nt][2] = -1e30f;
                if (c0 + 1 > limA + 8) sacc[nt][3] = -1e30f;
            }
        }

        float mxA = -1e30f, mxB = -1e30f;
#pragma unroll
        for (int nt = 0; nt < 8; nt++) {
            mxA = fmaxf(mxA, fmaxf(sacc[nt][0], sacc[nt][1]));
            mxB = fmaxf(mxB, fmaxf(sacc[nt][2], sacc[nt][3]));
        }
        mxA = fmaxf(mxA, __shfl_xor_sync(0xffffffffu, mxA, 1));
        mxA = fmaxf(mxA, __shfl_xor_sync(0xffffffffu, mxA, 2));
        mxB = fmaxf(mxB, __shfl_xor_sync(0xffffffffu, mxB, 1));
        mxB = fmaxf(mxB, __shfl_xor_sync(0xffffffffu, mxB, 2));
        float mnA = fmaxf(mA, mxA), mnB = fmaxf(mB, mxB);
        float aA = __expf(mA - mnA), aB = __expf(mB - mnB);

        uint32_t pa[4][4];
        float sA = 0.f, sB = 0.f;
#pragma unroll
        for (int k2 = 0; k2 < 4; k2++) {
            float p00 = __expf(sacc[2 * k2][0] - mnA);
            float p01 = __expf(sacc[2 * k2][1] - mnA);
            float p10 = __expf(sacc[2 * k2][2] - mnB);
            float p11 = __expf(sacc[2 * k2][3] - mnB);
            float p20 = __expf(sacc[2 * k2 + 1][0] - mnA);
            float p21 = __expf(sacc[2 * k2 + 1][1] - mnA);
            float p30 = __expf(sacc[2 * k2 + 1][2] - mnB);
            float p31 = __expf(sacc[2 * k2 + 1][3] - mnB);
            sA += p00 + p01 + p20 + p21;
            sB += p10 + p11 + p30 + p31;
            pa[k2][0] = h2pack(p00, p01);
            pa[k2][1] = h2pack(p10, p11);
            pa[k2][2] = h2pack(p20, p21);
            pa[k2][3] = h2pack(p30, p31);
        }
        sA += __shfl_xor_sync(0xffffffffu, sA, 1);
        sA += __shfl_xor_sync(0xffffffffu, sA, 2);
        sB += __shfl_xor_sync(0xffffffffu, sB, 1);
        sB += __shfl_xor_sync(0xffffffffu, sB, 2);
        lA = lA * aA + sA;
        lB = lB * aB + sB;
        mA = mnA; mB = mnB;

#pragma unroll
        for (int nt = 0; nt < 16; nt++) {
            oacc[nt][0] *= aA; oacc[nt][1] *= aA;
            oacc[nt][2] *= aB; oacc[nt][3] *= aB;
        }

#pragma unroll
        for (int k2 = 0; k2 < 4; k2++) {
#pragma unroll
            for (int p = 0; p < 8; p++) {
                uint32_t v0, v1, v2, v3;
                ldm_x4_t(Vs + (((uint32_t)(k2 * 16) + laneVr) * QSTR
                               + (uint32_t)(p * 16) + laneVc) * 2,
                         v0, v1, v2, v3);
                uint32_t vb0[2] = {v0, v1}, vb1[2] = {v2, v3};
                mma16816(oacc[2 * p],     pa[k2], vb0);
                mma16816(oacc[2 * p + 1], pa[k2], vb1);
            }
        }

        if (j + 1 < njt) CP_WAIT0;
        __syncthreads();
    }

    // epilogue: /l, v-orthogonalize (fp32 v from gmem), store y fp16
    {
        float invlA = 1.f / lA, invlB = 1.f / lB;
        const float* vAp = vlin + ((size_t)(b * T) + rowA) * (KVH * HD) + kvh * HD + colb;
        const float* vBp = vAp + (size_t)8 * (KVH * HD);
        float svA = 0.f, dyA = 0.f, svB = 0.f, dyB = 0.f;
#pragma unroll
        for (int nt = 0; nt < 16; nt++) {
            float2 va = *(const float2*)(vAp + nt * 8);
            float2 vb2 = *(const float2*)(vBp + nt * 8);
            svA += va.x * va.x + va.y * va.y;
            dyA += oacc[nt][0] * va.x + oacc[nt][1] * va.y;
            svB += vb2.x * vb2.x + vb2.y * vb2.y;
            dyB += oacc[nt][2] * vb2.x + oacc[nt][3] * vb2.y;
        }
        svA += __shfl_xor_sync(0xffffffffu, svA, 1);
        svA += __shfl_xor_sync(0xffffffffu, svA, 2);
        dyA += __shfl_xor_sync(0xffffffffu, dyA, 1);
        dyA += __shfl_xor_sync(0xffffffffu, dyA, 2);
        svB += __shfl_xor_sync(0xffffffffu, svB, 1);
        svB += __shfl_xor_sync(0xffffffffu, svB, 2);
        dyB += __shfl_xor_sync(0xffffffffu, dyB, 1);
        dyB += __shfl_xor_sync(0xffffffffu, dyB, 2);
        float coefA = (dyA * invlA) / fmaxf(svA, 1e-24f);
        float coefB = (dyB * invlB) / fmaxf(svB, 1e-24f);

        __half* yA = Y + ((size_t)(b * T) + rowA) * DIM + h * HD + colb;
        __half* yB = yA + (size_t)8 * DIM;
#pragma unroll
        for (int nt = 0; nt < 16; nt++) {
            float2 va = *(const float2*)(vAp + nt * 8);
            float2 vb2 = *(const float2*)(vBp + nt * 8);
            *(__half2*)(yA + nt * 8) = __floats2half2_rn(
                oacc[nt][0] * invlA - coefA * va.x,
                oacc[nt][1] * invlA - coefA * va.y);
            *(__half2*)(yB + nt * 8) = __floats2half2_rn(
                oacc[nt][2] * invlB - coefB * vb2.x,
                oacc[nt][3] * invlB - coefB * vb2.y);
        }
    }
}

// ---------------- launch -------------------------------------------------------
extern "C" void kernel_launch(void* const* d_in, const int* in_sizes, int n_in,
                              void* d_out, int out_size)
{
    const float* x    = (const float*)d_in[0];
    const float* Wq   = (const float*)d_in[1];
    const float* Wk   = (const float*)d_in[2];
    const float* Wv   = (const float*)d_in[3];
    const float* Wp   = (const float*)d_in[4];
    const float* gain = (const float*)d_in[5];

    float *qlin, *klin, *vlin;
    __half *q, *k, *v, *y, *xh, *wqh, *wkh, *wvh, *wph;
    cudaGetSymbolAddress((void**)&qlin, g_qlin);
    cudaGetSymbolAddress((void**)&klin, g_klin);
    cudaGetSymbolAddress((void**)&vlin, g_vlin);
    cudaGetSymbolAddress((void**)&q, g_q);
    cudaGetSymbolAddress((void**)&k, g_k);
    cudaGetSymbolAddress((void**)&v, g_v);
    cudaGetSymbolAddress((void**)&y, g_y);
    cudaGetSymbolAddress((void**)&xh, g_xh);
    cudaGetSymbolAddress((void**)&wqh, g_wqh);
    cudaGetSymbolAddress((void**)&wkh, g_wkh);
    cudaGetSymbolAddress((void**)&wvh, g_wvh);
    cudaGetSymbolAddress((void**)&wph, g_wph);

    cudaFuncSetAttribute(gemm_seg, cudaFuncAttributeMaxDynamicSharedMemorySize, GEMM_SMEM);
    cudaFuncSetAttribute(flash_kernel, cudaFuncAttributeMaxDynamicSharedMemorySize, FA_SMEM);

    // 0: fused fp16 conversion
    convert_all<<<(N4X + N4Q + N4K + N4V + N4P) / 256, 256>>>(
        x, Wq, Wk, Wv, Wp, xh, wqh, wkh, wvh, wph);

    // 1: fused QKV projection (N = 2048 + 512 + 512)
    gemm_seg<<<dim3(24, MTOT / 128), 256, GEMM_SMEM>>>(
        xh, DIM,
        wqh, qlin, 16, DIM,
        wkh, klin, 4, KVH * HD,
        wvh, vlin, 4, KVH * HD);

    // 2: fused rms+rope (q,k) + v reorder -> fp16
    rope_fused<<<(NWQ + NWK + NWV) / 4, 128>>>(qlin, klin, vlin, gain, q, k, v);

    // 3: flash attention (BQ=64, 3 CTAs/SM) + fused epilogue  (profiled)
    flash_kernel<<<dim3(T / 64, H, BATCH), 128, FA_SMEM>>>(q, k, v, vlin, y);

    // 4: output projection (y fp16 -> d_out fp32)
    gemm_seg<<<dim3(16, MTOT / 128), 256, GEMM_SMEM>>>(
        y, DIM,
        wph, (float*)d_out, 16, DIM,
        wph, (float*)d_out, 0, DIM,
        wph, (float*)d_out, 0, DIM);
}

// round 17
// speedup vs baseline: 1.0146x; 1.0146x over previous
#include <cuda_runtime.h>
#include <cuda_fp16.h>
#include <mma.h>
#include <math.h>
#include <cstdint>

using namespace nvcuda;

#define DIM 2048
#define H 16
#define KVH 4
#define HD 128
#define RD 64
#define BATCH 4
#define T 2048
#define MTOT (BATCH * T)   // 8192
#define SCALE 0.08838834764831845f
#define LOG2E 1.4426950408889634f
#define LOG2_10000 13.287712379549449f

// ---------------- scratch -----------------------------------------------------
__device__ float  g_qlin[MTOT * DIM];
__device__ float  g_klin[MTOT * KVH * HD];
__device__ float  g_vlin[MTOT * KVH * HD];
__device__ __half g_q[BATCH * H * T * HD];
__device__ __half g_k[BATCH * KVH * T * HD];
__device__ __half g_v[BATCH * KVH * T * HD];
__device__ __half g_y[MTOT * DIM];
__device__ __half g_xh[MTOT * DIM];
__device__ __half g_wqh[DIM * DIM];
__device__ __half g_wkh[KVH * HD * DIM];
__device__ __half g_wvh[KVH * HD * DIM];
__device__ __half g_wph[DIM * DIM];

// ---------------- helpers ------------------------------------------------------
__device__ __forceinline__ void cp_async16(void* smem, const void* gmem) {
    unsigned s = (unsigned)__cvta_generic_to_shared(smem);
    asm volatile("cp.async.cg.shared.global [%0], [%1], 16;\n" :: "r"(s), "l"(gmem) : "memory");
}
#define CP_COMMIT asm volatile("cp.async.commit_group;\n" ::: "memory")
#define CP_WAIT0  asm volatile("cp.async.wait_group 0;\n" ::: "memory")
#define CP_WAIT1  asm volatile("cp.async.wait_group 1;\n" ::: "memory")

__device__ __forceinline__ void ldm_x4(uint32_t a, uint32_t& r0, uint32_t& r1,
                                       uint32_t& r2, uint32_t& r3) {
    asm volatile("ldmatrix.sync.aligned.m8n8.x4.shared.b16 {%0,%1,%2,%3}, [%4];"
                 : "=r"(r0), "=r"(r1), "=r"(r2), "=r"(r3) : "r"(a));
}
__device__ __forceinline__ void ldm_x4_t(uint32_t a, uint32_t& r0, uint32_t& r1,
                                         uint32_t& r2, uint32_t& r3) {
    asm volatile("ldmatrix.sync.aligned.m8n8.x4.trans.shared.b16 {%0,%1,%2,%3}, [%4];"
                 : "=r"(r0), "=r"(r1), "=r"(r2), "=r"(r3) : "r"(a));
}
__device__ __forceinline__ void mma16816(float* c, const uint32_t* a, const uint32_t* b) {
    asm volatile("mma.sync.aligned.m16n8k16.row.col.f32.f16.f16.f32 "
                 "{%0,%1,%2,%3}, {%4,%5,%6,%7}, {%8,%9}, {%0,%1,%2,%3};"
                 : "+f"(c[0]), "+f"(c[1]), "+f"(c[2]), "+f"(c[3])
                 : "r"(a[0]), "r"(a[1]), "r"(a[2]), "r"(a[3]), "r"(b[0]), "r"(b[1]));
}
__device__ __forceinline__ uint32_t h2pack(float x, float y) {
    __half2 h = __floats2half2_rn(x, y);
    return *(uint32_t*)&h;
}

// ---------------- fused fp16 conversion of all GEMM operands -------------------
#define N4X 4194304
#define N4Q 1048576
#define N4K 262144
#define N4V 262144
#define N4P 1048576
__global__ void convert_all(
    const float* __restrict__ x, const float* __restrict__ wq,
    const float* __restrict__ wk, const float* __restrict__ wv,
    const float* __restrict__ wp,
    __half* __restrict__ xh, __half* __restrict__ wqh,
    __half* __restrict__ wkh, __half* __restrict__ wvh, __half* __restrict__ wph)
{
    int i = blockIdx.x * blockDim.x + threadIdx.x;
    const float4* src; __half2* dst; int off;
    if (i < N4X)                         { src = (const float4*)x;  dst = (__half2*)xh;  off = 0; }
    else if (i < N4X + N4Q)              { src = (const float4*)wq; dst = (__half2*)wqh; off = N4X; }
    else if (i < N4X + N4Q + N4K)        { src = (const float4*)wk; dst = (__half2*)wkh; off = N4X + N4Q; }
    else if (i < N4X + N4Q + N4K + N4V)  { src = (const float4*)wv; dst = (__half2*)wvh; off = N4X + N4Q + N4K; }
    else                                 { src = (const float4*)wp; dst = (__half2*)wph; off = N4X + N4Q + N4K + N4V; }
    int j = i - off;
    float4 v = src[j];
    dst[j * 2]     = __floats2half2_rn(v.x, v.y);
    dst[j * 2 + 1] = __floats2half2_rn(v.z, v.w);
}

// ---------------- FP16 GEMM, segmented N (round-10 config) ---------------------
#define GSTR 40
#define GSTG (128 * GSTR)
#define GEMM_SMEM (3 * 2 * GSTG * 2)      // 61440 bytes

__global__ void __launch_bounds__(256, 2) gemm_seg(
    const __half* __restrict__ A, int K,
    const __half* __restrict__ B0, float* __restrict__ C0, int t0, int ldc0,
    const __half* __restrict__ B1, float* __restrict__ C1, int t1, int ldc1,
    const __half* __restrict__ B2, float* __restrict__ C2, int t2, int ldc2)
{
    extern __shared__ __half hsm[];
    const int tid = threadIdx.x;
    const int warp = tid >> 5;
    const int wr = warp >> 2, wc = warp & 3;
    const int bm = blockIdx.y;
    int bn = blockIdx.x;

    const __half* B; float* C; int ldc;
    if (bn < t0)            { B = B0; C = C0; ldc = ldc0; }
    else if (bn < t0 + t1)  { B = B1; C = C1; ldc = ldc1; bn -= t0; }
    else                    { B = B2; C = C2; ldc = ldc2; bn -= t0 + t1; }

    const __half* Ab = A + (size_t)bm * 128 * K;
    const __half* Bb = B + (size_t)bn * 128 * K;

    wmma::fragment<wmma::accumulator, 16, 16, 16, float> acc[4][2];
#pragma unroll
    for (int i = 0; i < 4; i++)
#pragma unroll
        for (int j = 0; j < 2; j++) wmma::fill_fragment(acc[i][j], 0.0f);

    const int ntiles = K >> 5;
#pragma unroll
    for (int s = 0; s < 2; s++) {
        __half* As = hsm + s * 2 * GSTG;
        __half* Bs = As + GSTG;
#pragma unroll
        for (int i = 0; i < 2; i++) {
            int idx = tid + i * 256;
            int r = idx >> 2, c8 = (idx & 3) * 8;
            cp_async16(As + r * GSTR + c8, Ab + (size_t)r * K + s * 32 + c8);
            cp_async16(Bs + r * GSTR + c8, Bb + (size_t)r * K + s * 32 + c8);
        }
        CP_COMMIT;
    }

    for (int kt = 0; kt < ntiles; kt++) {
        CP_WAIT1;
        __syncthreads();
        __half* As = hsm + (kt % 3) * 2 * GSTG;
        __half* Bs = As + GSTG;
#pragma unroll
        for (int kk = 0; kk < 32; kk += 16) {
            wmma::fragment<wmma::matrix_a, 16, 16, 16, __half, wmma::row_major> a[4];
            wmma::fragment<wmma::matrix_b, 16, 16, 16, __half, wmma::col_major> bf[2];
#pragma unroll
            for (int i = 0; i < 4; i++)
                wmma::load_matrix_sync(a[i], As + (wr * 64 + i * 16) * GSTR + kk, GSTR);
#pragma unroll
            for (int j = 0; j < 2; j++)
                wmma::load_matrix_sync(bf[j], Bs + (wc * 32 + j * 16) * GSTR + kk, GSTR);
#pragma unroll
            for (int i = 0; i < 4; i++)
#pragma unroll
                for (int j = 0; j < 2; j++)
                    wmma::mma_sync(acc[i][j], a[i], bf[j], acc[i][j]);
        }
        __syncthreads();
        if (kt + 2 < ntiles) {
            int s = (kt + 2) % 3;
            int k0 = (kt + 2) * 32;
            __half* An = hsm + s * 2 * GSTG;
            __half* Bn = An + GSTG;
#pragma unroll
            for (int i = 0; i < 2; i++) {
                int idx = tid + i * 256;
                int r = idx >> 2, c8 = (idx & 3) * 8;
                cp_async16(An + r * GSTR + c8, Ab + (size_t)r * K + k0 + c8);
                cp_async16(Bn + r * GSTR + c8, Bb + (size_t)r * K + k0 + c8);
            }
        }
        CP_COMMIT;
    }

#pragma unroll
    for (int i = 0; i < 4; i++)
#pragma unroll
        for (int j = 0; j < 2; j++)
            wmma::store_matrix_sync(
                C + (size_t)(bm * 128 + wr * 64 + i * 16) * ldc + bn * 128 + wc * 32 + j * 16,
                acc[i][j], ldc, wmma::mem_row_major);
}

// ---------------- fused RMSNorm+RoPE (q,k) + v reorder, fp16 out ---------------
// q additionally pre-scaled by SCALE*LOG2E so flash softmax uses bare exp2f.
#define NWQ (BATCH * T * H)
#define NWK (BATCH * T * KVH)
#define NWV (BATCH * T * KVH)
__global__ void rope_fused(
    const float* __restrict__ qlin, const float* __restrict__ klin,
    const float* __restrict__ vlin, const float* __restrict__ gain,
    __half* __restrict__ qout, __half* __restrict__ kout, __half* __restrict__ vout)
{
    int w = (blockIdx.x * blockDim.x + threadIdx.x) >> 5;
    int lane = threadIdx.x & 31;

    if (w < NWQ + NWK) {
        bool isq = (w < NWQ);
        int hh, t, b, nh;
        const float* src;
        if (isq) {
            nh = H;
            hh = w % H; t = (w / H) % T; b = w / (H * T);
            src = qlin + ((size_t)(b * T + t)) * DIM + hh * HD;
        } else {
            int wk = w - NWQ;
            nh = KVH;
            hh = wk % KVH; t = (wk / KVH) % T; b = wk / (KVH * T);
            src = klin + ((size_t)(b * T + t)) * (KVH * HD) + hh * HD;
        }
        float v0 = src[lane], v1 = src[lane + 32], v2 = src[lane + 64], v3 = src[lane + 96];
        float ss = v0 * v0 + v1 * v1 + v2 * v2 + v3 * v3;
#pragma unroll
        for (int o = 16; o; o >>= 1) ss += __shfl_xor_sync(0xffffffffu, ss, o);
        float r = rsqrtf(ss * (1.0f / 128.0f) + 1e-6f);
        v0 *= r; v1 *= r; v2 *= r; v3 *= r;

        float inv = exp2f(-(float)lane * (LOG2_10000 / 32.0f));
        float fr = (float)t * inv;
        float sn, cs;
        sincosf(fr, &sn, &cs);
        float o0 = v0 * cs - v1 * sn;
        float o1 = v1 * cs + v0 * sn;

        float g = isq ? gain[hh] * SCALE * LOG2E : 1.0f;
        __half* dst = (isq ? qout : kout) + (((size_t)(b * nh + hh)) * T + t) * HD;
        dst[lane]      = __float2half_rn(o0 * g);
        dst[lane + 32] = __float2half_rn(o1 * g);
        dst[lane + 64] = __float2half_rn(v2 * g);
        dst[lane + 96] = __float2half_rn(v3 * g);
    } else {
        int u = w - NWQ - NWK;
        int kv = u & 3;
        int bt = u >> 2;
        int t = bt & (T - 1);
        int b = bt >> 11;
        float4 val = ((const float4*)vlin)[u * 32 + lane];
        __half2* dst = (__half2*)(vout + (((size_t)(b * KVH + kv)) * T + t) * HD);
        dst[lane * 2]     = __floats2half2_rn(val.x, val.y);
        dst[lane * 2 + 1] = __floats2half2_rn(val.z, val.w);
    }
}

// ---------------- Flash attention FA2-style (BQ=64, BKV=64, 128 thr) -----------
// R15 config: smem 87040 B, 2 CTAs/SM. Softmax in exp2 domain (log2e folded
// into q), so all exponentials are bare MUFU.EX2.
#define QSTR 136
#define FA_SMEM 87040

__global__ void __launch_bounds__(128) flash_kernel(
    const __half* __restrict__ Q, const __half* __restrict__ Kg,
    const __half* __restrict__ Vg, const float* __restrict__ vlin,
    __half* __restrict__ Y)
{
    extern __shared__ char sm[];
    const uint32_t smem_base = (uint32_t)__cvta_generic_to_shared(sm);
    const uint32_t Ks_base = smem_base + 17408;
    const uint32_t Vs_base = smem_base + 52224;

    const int tid = threadIdx.x;
    const int warp = tid >> 5;      // 0..3, owns q rows [warp*16, +16)
    const int lane = tid & 31;
    const int qi = (gridDim.x - 1) - blockIdx.x;   // heavy tiles first
    const int h = blockIdx.y, b = blockIdx.z;
    const int q0 = qi * 64;
    const int kvh = h >> 2;
    const int njt = qi + 1;

    const __half* Qbase = Q + (((size_t)b * H + h) * T + q0) * HD;
    const __half* Kbase = Kg + ((size_t)b * KVH + kvh) * T * HD;
    const __half* Vbase = Vg + ((size_t)b * KVH + kvh) * T * HD;

#pragma unroll
    for (int i = 0; i < 8; i++) {
        int idx = tid + i * 128;
        int r = idx >> 4, c = idx & 15;
        cp_async16(sm + 17408 + r * 272 + c * 16, Kbase + r * 128 + c * 8);
        cp_async16(sm + 52224 + r * 272 + c * 16, Vbase + r * 128 + c * 8);
    }
    CP_COMMIT;
#pragma unroll
    for (int i = 0; i < 8; i++) {
        int idx = tid + i * 128;
        int r = idx >> 4, c = idx & 15;
        cp_async16(sm + r * 272 + c * 16, Qbase + r * 128 + c * 8);
    }
    CP_COMMIT;
    CP_WAIT0;
    __syncthreads();

    uint32_t qf[8][4];
    {
        uint32_t qaddr = smem_base +
            ((uint32_t)(warp * 16 + (lane & 15)) * QSTR + (uint32_t)(lane >> 4) * 8) * 2;
#pragma unroll
        for (int kk = 0; kk < 8; kk++)
            ldm_x4(qaddr + kk * 32, qf[kk][0], qf[kk][1], qf[kk][2], qf[kk][3]);
    }

    const int g8 = lane >> 3, l8 = lane & 7;
    const uint32_t laneK = (uint32_t)(((g8 >= 2) ? 8 : 0) + l8) * QSTR + ((g8 & 1) ? 8 : 0);
    const uint32_t laneVr = (uint32_t)((g8 & 1) * 8 + l8);
    const uint32_t laneVc = (g8 >= 2) ? 8 : 0;

    const int rowA = q0 + warp * 16 + (lane >> 2);
    const int colb = (lane & 3) * 2;

    float oacc[16][4];
#pragma unroll
    for (int nt = 0; nt < 16; nt++)
#pragma unroll
        for (int e = 0; e < 4; e++) oacc[nt][e] = 0.f;
    float mA = -1e30f, mB = -1e30f, lA = 0.f, lB = 0.f;

    for (int j = 0; j < njt; j++) {
        const int buf = j & 1;
        const uint32_t Ks = Ks_base + buf * 17408;
        const uint32_t Vs = Vs_base + buf * 17408;
        const int kbase = j * 64;

        if (j + 1 < njt) {
            const __half* Kn = Kbase + (size_t)(j + 1) * 8192;
            const __half* Vn = Vbase + (size_t)(j + 1) * 8192;
            char* Kd = sm + 17408 + (buf ^ 1) * 17408;
            char* Vd = sm + 52224 + (buf ^ 1) * 17408;
#pragma unroll
            for (int i = 0; i < 8; i++) {
                int idx = tid + i * 128;
                int r = idx >> 4, c = idx & 15;
                cp_async16(Kd + r * 272 + c * 16, Kn + r * 128 + c * 8);
                cp_async16(Vd + r * 272 + c * 16, Vn + r * 128 + c * 8);
            }
            CP_COMMIT;
        }

        float sacc[8][4];
#pragma unroll
        for (int nt = 0; nt < 8; nt++)
#pragma unroll
            for (int e = 0; e < 4; e++) sacc[nt][e] = 0.f;
#pragma unroll
        for (int kk = 0; kk < 8; kk++) {
#pragma unroll
            for (int p = 0; p < 4; p++) {
                uint32_t b0, b1, b2, b3;
                ldm_x4(Ks + ((uint32_t)(p * 16) * QSTR + (uint32_t)(kk * 16) + laneK) * 2,
                       b0, b1, b2, b3);
                uint32_t bb0[2] = {b0, b1}, bb1[2] = {b2, b3};
                mma16816(sacc[2 * p],     qf[kk], bb0);
                mma16816(sacc[2 * p + 1], qf[kk], bb1);
            }
        }

        if (kbase + 63 > rowA) {
            int limA = rowA - kbase;
#pragma unroll
            for (int nt = 0; nt < 8; nt++) {
                int c0 = nt * 8 + colb;
                if (c0 > limA)     sacc[nt][0] = -1e30f;
                if (c0 + 1 > limA) sacc[nt][1] = -1e30f;
                if (c0 > limA + 8)     sacc[nt][2] = -1e30f;
                if (c0 + 1 > limA + 8) sacc[nt][3] = -1e30f;
            }
        }

        float mxA = -1e30f, mxB = -1e30f;
#pragma unroll
        for (int nt = 0; nt < 8; nt++) {
            mxA = fmaxf(mxA, fmaxf(sacc[nt][0], sacc[nt][1]));
            mxB = fmaxf(mxB, fmaxf(sacc[nt][2], sacc[nt][3]));
        }
        mxA = fmaxf(mxA, __shfl_xor_sync(0xffffffffu, mxA, 1));
        mxA = fmaxf(mxA, __shfl_xor_sync(0xffffffffu, mxA, 2));
        mxB = fmaxf(mxB, __shfl_xor_sync(0xffffffffu, mxB, 1));
        mxB = fmaxf(mxB, __shfl_xor_sync(0xffffffffu, mxB, 2));
        float mnA = fmaxf(mA, mxA), mnB = fmaxf(mB, mxB);
        float aA = exp2f(mA - mnA), aB = exp2f(mB - mnB);

        uint32_t pa[4][4];
        float sA = 0.f, sB = 0.f;
#pragma unroll
        for (int k2 = 0; k2 < 4; k2++) {
            float p00 = exp2f(sacc[2 * k2][0] - mnA);
            float p01 = exp2f(sacc[2 * k2][1] - mnA);
            float p10 = exp2f(sacc[2 * k2][2] - mnB);
            float p11 = exp2f(sacc[2 * k2][3] - mnB);
            float p20 = exp2f(sacc[2 * k2 + 1][0] - mnA);
            float p21 = exp2f(sacc[2 * k2 + 1][1] - mnA);
            float p30 = exp2f(sacc[2 * k2 + 1][2] - mnB);
            float p31 = exp2f(sacc[2 * k2 + 1][3] - mnB);
            sA += p00 + p01 + p20 + p21;
            sB += p10 + p11 + p30 + p31;
            pa[k2][0] = h2pack(p00, p01);
            pa[k2][1] = h2pack(p10, p11);
            pa[k2][2] = h2pack(p20, p21);
            pa[k2][3] = h2pack(p30, p31);
        }
        sA += __shfl_xor_sync(0xffffffffu, sA, 1);
        sA += __shfl_xor_sync(0xffffffffu, sA, 2);
        sB += __shfl_xor_sync(0xffffffffu, sB, 1);
        sB += __shfl_xor_sync(0xffffffffu, sB, 2);
        lA = lA * aA + sA;
        lB = lB * aB + sB;
        mA = mnA; mB = mnB;

#pragma unroll
        for (int nt = 0; nt < 16; nt++) {
            oacc[nt][0] *= aA; oacc[nt][1] *= aA;
            oacc[nt][2] *= aB; oacc[nt][3] *= aB;
        }

#pragma unroll
        for (int k2 = 0; k2 < 4; k2++) {
#pragma unroll
            for (int p = 0; p < 8; p++) {
                uint32_t v0, v1, v2, v3;
                ldm_x4_t(Vs + (((uint32_t)(k2 * 16) + laneVr) * QSTR
                               + (uint32_t)(p * 16) + laneVc) * 2,
                         v0, v1, v2, v3);
                uint32_t vb0[2] = {v0, v1}, vb1[2] = {v2, v3};
                mma16816(oacc[2 * p],     pa[k2], vb0);
                mma16816(oacc[2 * p + 1], pa[k2], vb1);
            }
        }

        if (j + 1 < njt) CP_WAIT0;
        __syncthreads();
    }

    // epilogue: /l, v-orthogonalize (fp32 v from gmem), store y fp16
    {
        float invlA = 1.f / lA, invlB = 1.f / lB;
        const float* vAp = vlin + ((size_t)(b * T) + rowA) * (KVH * HD) + kvh * HD + colb;
        const float* vBp = vAp + (size_t)8 * (KVH * HD);
        float svA = 0.f, dyA = 0.f, svB = 0.f, dyB = 0.f;
#pragma unroll
        for (int nt = 0; nt < 16; nt++) {
            float2 va = *(const float2*)(vAp + nt * 8);
            float2 vb2 = *(const float2*)(vBp + nt * 8);
            svA += va.x * va.x + va.y * va.y;
            dyA += oacc[nt][0] * va.x + oacc[nt][1] * va.y;
            svB += vb2.x * vb2.x + vb2.y * vb2.y;
            dyB += oacc[nt][2] * vb2.x + oacc[nt][3] * vb2.y;
        }
        svA += __shfl_xor_sync(0xffffffffu, svA, 1);
        svA += __shfl_xor_sync(0xffffffffu, svA, 2);
        dyA += __shfl_xor_sync(0xffffffffu, dyA, 1);
        dyA += __shfl_xor_sync(0xffffffffu, dyA, 2);
        svB += __shfl_xor_sync(0xffffffffu, svB, 1);
        svB += __shfl_xor_sync(0xffffffffu, svB, 2);
        dyB += __shfl_xor_sync(0xffffffffu, dyB, 1);
        dyB += __shfl_xor_sync(0xffffffffu, dyB, 2);
        float coefA = (dyA * invlA) / fmaxf(svA, 1e-24f);
        float coefB = (dyB * invlB) / fmaxf(svB, 1e-24f);

        __half* yA = Y + ((size_t)(b * T) + rowA) * DIM + h * HD + colb;
        __half* yB = yA + (size_t)8 * DIM;
#pragma unroll
        for (int nt = 0; nt < 16; nt++) {
            float2 va = *(const float2*)(vAp + nt * 8);
            float2 vb2 = *(const float2*)(vBp + nt * 8);
            *(__half2*)(yA + nt * 8) = __floats2half2_rn(
                oacc[nt][0] * invlA - coefA * va.x,
                oacc[nt][1] * invlA - coefA * va.y);
            *(__half2*)(yB + nt * 8) = __floats2half2_rn(
                oacc[nt][2] * invlB - coefB * vb2.x,
                oacc[nt][3] * invlB - coefB * vb2.y);
        }
    }
}

// ---------------- launch -------------------------------------------------------
extern "C" void kernel_launch(void* const* d_in, const int* in_sizes, int n_in,
                              void* d_out, int out_size)
{
    const float* x    = (const float*)d_in[0];
    const float* Wq   = (const float*)d_in[1];
    const float* Wk   = (const float*)d_in[2];
    const float* Wv   = (const float*)d_in[3];
    const float* Wp   = (const float*)d_in[4];
    const float* gain = (const float*)d_in[5];

    float *qlin, *klin, *vlin;
    __half *q, *k, *v, *y, *xh, *wqh, *wkh, *wvh, *wph;
    cudaGetSymbolAddress((void**)&qlin, g_qlin);
    cudaGetSymbolAddress((void**)&klin, g_klin);
    cudaGetSymbolAddress((void**)&vlin, g_vlin);
    cudaGetSymbolAddress((void**)&q, g_q);
    cudaGetSymbolAddress((void**)&k, g_k);
    cudaGetSymbolAddress((void**)&v, g_v);
    cudaGetSymbolAddress((void**)&y, g_y);
    cudaGetSymbolAddress((void**)&xh, g_xh);
    cudaGetSymbolAddress((void**)&wqh, g_wqh);
    cudaGetSymbolAddress((void**)&wkh, g_wkh);
    cudaGetSymbolAddress((void**)&wvh, g_wvh);
    cudaGetSymbolAddress((void**)&wph, g_wph);

    cudaFuncSetAttribute(gemm_seg, cudaFuncAttributeMaxDynamicSharedMemorySize, GEMM_SMEM);
    cudaFuncSetAttribute(flash_kernel, cudaFuncAttributeMaxDynamicSharedMemorySize, FA_SMEM);

    // 0: fused fp16 conversion
    convert_all<<<(N4X + N4Q + N4K + N4V + N4P) / 256, 256>>>(
        x, Wq, Wk, Wv, Wp, xh, wqh, wkh, wvh, wph);

    // 1: fused QKV projection (N = 2048 + 512 + 512)
    gemm_seg<<<dim3(24, MTOT / 128), 256, GEMM_SMEM>>>(
        xh, DIM,
        wqh, qlin, 16, DIM,
        wkh, klin, 4, KVH * HD,
        wvh, vlin, 4, KVH * HD);

    // 2: fused rms+rope (q,k) + v reorder -> fp16  (q pre-scaled by SCALE*log2e)
    rope_fused<<<(NWQ + NWK + NWV) / 4, 128>>>(qlin, klin, vlin, gain, q, k, v);

    // 3: flash attention (BQ=64, 2 CTAs/SM, exp2-domain softmax)  (profiled)
    flash_kernel<<<dim3(T / 64, H, BATCH), 128, FA_SMEM>>>(q, k, v, vlin, y);

    // 4: output projection (y fp16 -> d_out fp32)
    gemm_seg<<<dim3(16, MTOT / 128), 256, GEMM_SMEM>>>(
        y, DIM,
        wph, (float*)d_out, 16, DIM,
        wph, (float*)d_out, 0, DIM,
        wph, (float*)d_out, 0, DIM);
}